// round 12
// baseline (speedup 1.0000x reference)
#include <cuda_runtime.h>
#include <cuda_bf16.h>

// Problem constants
#define BATCH 256
#define TT    1024
#define INP   128
#define LAT   64
#define HID   128
#define OUTD  32

// Scratch: drive[b][t][l] (fp32), 64 MB (each block writes only its own slab)
__device__ float g_drive[(size_t)BATCH * TT * LAT];

// ---------- f32x2 helpers ----------
__device__ __forceinline__ void fma2(unsigned long long& acc,
                                     unsigned long long a,
                                     unsigned long long b) {
    asm("fma.rn.f32x2 %0, %1, %2, %0;" : "+l"(acc) : "l"(a), "l"(b));
}
__device__ __forceinline__ float psum2(unsigned long long v) {
    float lo, hi;
    asm("mov.b64 {%0,%1}, %2;" : "=f"(lo), "=f"(hi) : "l"(v));
    return lo + hi;
}
__device__ __forceinline__ unsigned long long pack2(float lo, float hi) {
    unsigned long long r;
    asm("mov.b64 %0, {%1,%2};" : "=l"(r) : "f"(lo), "f"(hi));
    return r;
}
__device__ __forceinline__ void gbar(int id) {
    asm volatile("bar.sync %0, 256;" :: "r"(id) : "memory");
}

// Scan smem geometry (proven conflict-free in R7-R11)
#define ZST 36
#define HST 18

// Dynamic smem layout (bytes)
#define AS_OFF   0
#define AS_BYTES (256 * 132 * 4)            // 135168
#define CQ_OFF   AS_BYTES
#define CQ_BYTES (32 * 64 * 16)             // 32768
#define ZB_OFF   (CQ_OFF + CQ_BYTES)        // 167936
#define ZB_BYTES (2 * 8 * ZST * 4)          // 2304
#define HB_OFF   (ZB_OFF + ZB_BYTES)        // 170240
#define HB_BYTES (2 * 16 * HST * 4)         // 2304
#define SMEM_TOTAL (HB_OFF + HB_BYTES)      // 172544

// =====================================================================
// Fused kernel: per-block drive prologue (u = s @ C^T for own 2 batches)
// followed by the scan. 128 blocks x 512 threads. No separate launch.
// =====================================================================
__global__ void __launch_bounds__(512, 1)
fused_kernel(const float* __restrict__ inp,  const float* __restrict__ Ag,
             const float* __restrict__ W1g,  const float* __restrict__ W2g,
             const float* __restrict__ h1g,  const float* __restrict__ h2g,
             const float* __restrict__ Cg,   const float* __restrict__ Woutg,
             const float* __restrict__ boutg, float* __restrict__ outg) {
    extern __shared__ char dsm[];
    float*      As   = reinterpret_cast<float*>(dsm + AS_OFF);       // [256][132]
    ulonglong2* Cq   = reinterpret_cast<ulonglong2*>(dsm + CQ_OFF);  // [32 q][64 csw]
    float (*zbuf)[8 * ZST]  = reinterpret_cast<float(*)[8 * ZST]>(dsm + ZB_OFF);
    float (*hbuf)[16 * HST] = reinterpret_cast<float(*)[16 * HST]>(dsm + HB_OFF);

    const int tid = threadIdx.x;

    // ================= PROLOGUE: u-slab GEMM for own 2 batches ========
    {
        const size_t slab = (size_t)blockIdx.x * 2048;   // (b,t) rows

        // stage C once: Cq[q][(col&7)*8 + col>>3] = jp-pair of C[col][4q..4q+3]
        for (int idx = tid; idx < 2048; idx += 512) {
            int col = idx >> 5;
            int q4  = idx & 31;
            float4 v = reinterpret_cast<const float4*>(Cg)[idx];
            int csw = (col & 7) * 8 + (col >> 3);
            ulonglong2 p;
            p.x = pack2(v.x, v.y);
            p.y = pack2(v.z, v.w);
            Cq[q4 * 64 + csw] = p;
        }

        const int ctx = tid & 7;     // col group: cols ctx*8..+7
        const int rt  = tid >> 3;    // row base: rows rt + 64k, k=0..3

        #pragma unroll 1
        for (int tile = 0; tile < 8; ++tile) {
            const size_t r0 = slab + (size_t)tile * 256;
            __syncthreads();   // WAR: prev tile's As reads done (and Cq staged)
            for (int e = tid; e < 8192; e += 512) {
                int row = e >> 5;
                int q4  = e & 31;
                float4 v = reinterpret_cast<const float4*>(
                    inp + (r0 + row) * INP)[q4];
                *reinterpret_cast<float4*>(&As[row * 132 + q4 * 4]) = v;
            }
            __syncthreads();

            unsigned long long acc[4][8];
            #pragma unroll
            for (int k = 0; k < 4; ++k)
                #pragma unroll
                for (int c = 0; c < 8; ++c) acc[k][c] = 0ull;

            #pragma unroll 2
            for (int q = 0; q < 32; ++q) {
                ulonglong2 cw[8];
                #pragma unroll
                for (int c = 0; c < 8; ++c)
                    cw[c] = Cq[q * 64 + c * 8 + ctx];
                ulonglong2 av[4];
                #pragma unroll
                for (int k = 0; k < 4; ++k)
                    av[k] = *reinterpret_cast<const ulonglong2*>(
                        &As[(rt + 64 * k) * 132 + 4 * q]);
                #pragma unroll
                for (int k = 0; k < 4; ++k)
                    #pragma unroll
                    for (int c = 0; c < 8; ++c) {
                        fma2(acc[k][c], av[k].x, cw[c].x);
                        fma2(acc[k][c], av[k].y, cw[c].y);
                    }
            }

            #pragma unroll
            for (int k = 0; k < 4; ++k) {
                size_t grow = r0 + rt + 64 * k;
                float4 o0, o1;
                o0.x = psum2(acc[k][0]); o0.y = psum2(acc[k][1]);
                o0.z = psum2(acc[k][2]); o0.w = psum2(acc[k][3]);
                o1.x = psum2(acc[k][4]); o1.y = psum2(acc[k][5]);
                o1.z = psum2(acc[k][6]); o1.w = psum2(acc[k][7]);
                float* dst = &g_drive[grow * LAT + ctx * 8];
                reinterpret_cast<float4*>(dst)[0] = o0;
                reinterpret_cast<float4*>(dst)[1] = o1;
            }
        }
        __syncthreads();   // orders block's global writes before scan reads
    }

    // ================= SCAN (identical to R11 recur) ===================
    const int gid = tid >> 8;
    const int c   = tid & 255;
    const int bat = blockIdx.x * 2 + gid;
    const int barid = 1 + gid;

    // phase1 mapping
    const int kc1 = c & 7;
    const int rg1 = c >> 3;
    const int b4a = (c >> 2) & 1;
    const int b2a = (c >> 1) & 1;
    const int hrow = 4 * rg1 + 2 * b4a + b2a;

    // phase2 mapping
    const int kc2 = c & 15;
    const int rg2 = c >> 4;
    const int b1b = c & 1;
    const int b2b = (c >> 1) & 1;
    const int lz  = 4 * rg2 + 2 * b1b + b2b;

    unsigned long long w2r[4][4];
    #pragma unroll
    for (int r = 0; r < 4; ++r)
        #pragma unroll
        for (int j = 0; j < 4; ++j)
            w2r[r][j] = *reinterpret_cast<const unsigned long long*>(
                &W2g[(4 * rg1 + r) * LAT + 8 * kc1 + 2 * j]);
    unsigned long long w1r[4][4];
    #pragma unroll
    for (int r = 0; r < 4; ++r)
        #pragma unroll
        for (int j = 0; j < 4; ++j)
            w1r[r][j] = *reinterpret_cast<const unsigned long long*>(
                &W1g[(4 * rg2 + r) * HID + 8 * kc2 + 2 * j]);

    const float h2c = h2g[hrow];
    const float Ac  = Ag[lz];
    const float h1c = h1g[lz];

    if ((c & 12) == 0) zbuf[gid][(lz >> 3) * ZST + (lz & 7)] = 0.0f;
    __syncthreads();

    const float* zptr = &zbuf[gid][kc1 * ZST];
    const unsigned long long* hptr =
        reinterpret_cast<const unsigned long long*>(&hbuf[gid][kc2 * HST]);

    float zprev = 0.0f;
    const size_t ubase = ((size_t)bat) * TT * LAT + lz;
    float u_cur = g_drive[ubase] + h1c;
    float u_nxt = g_drive[ubase + LAT] + h1c;

    const unsigned FULL = 0xffffffffu;

    for (int t = 0; t < TT; ++t) {
        const int tp = (t + 2 < TT) ? (t + 2) : (TT - 1);
        float u_fut = g_drive[ubase + (size_t)tp * LAT] + h1c;

        // ======== phase 1: hidden = relu(z @ W2^T + h2) ========
        {
            ulonglong2 za = *reinterpret_cast<const ulonglong2*>(zptr);
            ulonglong2 zb = *reinterpret_cast<const ulonglong2*>(zptr + 4);
            float p[4];
            #pragma unroll
            for (int r = 0; r < 4; ++r) {
                unsigned long long acc = 0ull;
                fma2(acc, za.x, w2r[r][0]);
                fma2(acc, za.y, w2r[r][1]);
                fma2(acc, zb.x, w2r[r][2]);
                fma2(acc, zb.y, w2r[r][3]);
                p[r] = psum2(acc);
            }
            float s0 = b4a ? p[0] : p[2];
            float r0 = __shfl_xor_sync(FULL, s0, 4);
            float s1 = b4a ? p[1] : p[3];
            float r1 = __shfl_xor_sync(FULL, s1, 4);
            float q0 = (b4a ? p[2] : p[0]) + r0;
            float q1 = (b4a ? p[3] : p[1]) + r1;
            float s2 = b2a ? q0 : q1;
            float r2 = __shfl_xor_sync(FULL, s2, 2);
            float s  = (b2a ? q1 : q0) + r2;
            s += __shfl_xor_sync(FULL, s, 1);
            float hval = fmaxf(s + h2c, 0.0f);
            if (!(c & 1))
                hbuf[gid][(hrow >> 3) * HST + (hrow & 7)] = hval;
        }
        gbar(barid);

        // ======== phase 2: z' = clip(z*A + hidden @ W1^T + (h1+u)) ========
        {
            unsigned long long h0 = hptr[0];
            unsigned long long h1v = hptr[1];
            unsigned long long h2v = hptr[2];
            unsigned long long h3v = hptr[3];
            float p[4];
            #pragma unroll
            for (int r = 0; r < 4; ++r) {
                unsigned long long acc = 0ull;
                fma2(acc, h0,  w1r[r][0]);
                fma2(acc, h1v, w1r[r][1]);
                fma2(acc, h2v, w1r[r][2]);
                fma2(acc, h3v, w1r[r][3]);
                p[r] = psum2(acc);
            }
            float s0 = b1b ? p[0] : p[2];
            float r0 = __shfl_xor_sync(FULL, s0, 1);
            float s1 = b1b ? p[1] : p[3];
            float r1 = __shfl_xor_sync(FULL, s1, 1);
            float q0 = (b1b ? p[2] : p[0]) + r0;
            float q1 = (b1b ? p[3] : p[1]) + r1;
            float s2 = b2b ? q0 : q1;
            float r2 = __shfl_xor_sync(FULL, s2, 2);
            float v  = (b2b ? q1 : q0) + r2;
            v += __shfl_xor_sync(FULL, v, 4);
            v += __shfl_xor_sync(FULL, v, 8);

            float zn = zprev * Ac + (v + u_cur);
            zn = fminf(5.0f, fmaxf(-5.0f, zn));
            zprev = zn;
            if ((c & 12) == 0)
                zbuf[gid][(lz >> 3) * ZST + (lz & 7)] = zn;
        }
        u_cur = u_nxt;
        u_nxt = u_fut;
        gbar(barid);
    }

    // ---- epilogue: out[bat][o] = zT . Wout[o] + bout[o]
    if (c < OUTD) {
        const int o = c;
        float acc = boutg[o];
        #pragma unroll
        for (int l = 0; l < LAT; ++l)
            acc += zbuf[gid][(l >> 3) * ZST + (l & 7)] * Woutg[o * LAT + l];
        outg[(size_t)bat * OUTD + o] = acc;
    }
}

// =====================================================================
extern "C" void kernel_launch(void* const* d_in, const int* in_sizes, int n_in,
                              void* d_out, int out_size) {
    (void)in_sizes; (void)n_in; (void)out_size;
    const float* inp   = (const float*)d_in[0];
    const float* Ag    = (const float*)d_in[1];
    const float* W1g   = (const float*)d_in[2];
    const float* W2g   = (const float*)d_in[3];
    const float* h1g   = (const float*)d_in[4];
    const float* h2g   = (const float*)d_in[5];
    const float* Cg    = (const float*)d_in[6];
    const float* Woutg = (const float*)d_in[7];
    const float* boutg = (const float*)d_in[8];
    float* outg = (float*)d_out;

    cudaFuncSetAttribute(fused_kernel,
                         cudaFuncAttributeMaxDynamicSharedMemorySize, SMEM_TOTAL);
    fused_kernel<<<BATCH / 2, 512, SMEM_TOTAL>>>(inp, Ag, W1g, W2g, h1g, h2g,
                                                 Cg, Woutg, boutg, outg);
}

// round 13
// speedup vs baseline: 1.0598x; 1.0598x over previous
#include <cuda_runtime.h>
#include <cuda_bf16.h>

// Problem constants
#define BATCH 256
#define TT    1024
#define INP   128
#define LAT   64
#define HID   128
#define OUTD  32

// Scratch: drive[b][t][l] (fp32), 64 MB
__device__ float g_drive[(size_t)BATCH * TT * LAT];

// ---------- f32x2 helpers ----------
__device__ __forceinline__ void fma2(unsigned long long& acc,
                                     unsigned long long a,
                                     unsigned long long b) {
    asm("fma.rn.f32x2 %0, %1, %2, %0;" : "+l"(acc) : "l"(a), "l"(b));
}
__device__ __forceinline__ float psum2(unsigned long long v) {
    float lo, hi;
    asm("mov.b64 {%0,%1}, %2;" : "=f"(lo), "=f"(hi) : "l"(v));
    return lo + hi;
}
__device__ __forceinline__ unsigned long long pack2(float lo, float hi) {
    unsigned long long r;
    asm("mov.b64 %0, {%1,%2};" : "=l"(r) : "f"(lo), "f"(hi));
    return r;
}
__device__ __forceinline__ void gbar(int id) {
    asm volatile("bar.sync %0, 256;" :: "r"(id) : "memory");
}
// ---------- cp.async helpers ----------
__device__ __forceinline__ void cp16(void* smem_dst, const void* gsrc) {
    unsigned saddr = (unsigned)__cvta_generic_to_shared(smem_dst);
    asm volatile("cp.async.cg.shared.global [%0], [%1], 16;"
                 :: "r"(saddr), "l"(gsrc) : "memory");
}
#define CP_COMMIT() asm volatile("cp.async.commit_group;" ::: "memory")
#define CP_WAIT1()  asm volatile("cp.async.wait_group 1;" ::: "memory")
#define CP_WAIT0()  asm volatile("cp.async.wait_group 0;" ::: "memory")

// =====================================================================
// Kernel 1: PERSISTENT drive = input @ C^T  -> g_drive
// 148 blocks x 128 threads, 1 block/SM. Each block loops ~14 tiles of
// 128 rows, double-buffered via cp.async (stage n+1 during compute n).
// Compute: R11's balanced 8x8 jp-pair tile (LDS.128 conflict-free).
// =====================================================================
#define AST 132
#define NTILES 2048
#define NBLK   148
#define AS_TILE (128 * AST)                 // floats per buffer

__global__ void __launch_bounds__(128, 1)
drive_kernel(const float* __restrict__ inp, const float* __restrict__ Cg) {
    extern __shared__ char dsm[];
    float*      As = reinterpret_cast<float*>(dsm);                      // [2][128*AST]
    ulonglong2* Cq = reinterpret_cast<ulonglong2*>(dsm + 2 * AS_TILE * 4);

    const int tid = threadIdx.x;

    // stage C once: Cq[q][(col&7)*8 + col>>3] = jp-pair of C[col][4q..4q+3]
    for (int idx = tid; idx < 2048; idx += 128) {
        int col = idx >> 5;
        int q4  = idx & 31;
        float4 v = reinterpret_cast<const float4*>(Cg)[idx];
        int csw = (col & 7) * 8 + (col >> 3);
        ulonglong2 p;
        p.x = pack2(v.x, v.y);
        p.y = pack2(v.z, v.w);
        Cq[q4 * 64 + csw] = p;
    }

    const int ctx = tid & 7;       // col group: cols ctx*8..+7
    const int rt  = tid >> 3;      // row base: rows rt + 16k, k=0..7

    // prologue: stage first tile into buf 0
    {
        const float* src = inp + (size_t)blockIdx.x * 128 * INP;
        #pragma unroll
        for (int i = 0; i < 32; ++i) {
            int e = tid + i * 128;
            int row = e >> 5;
            int q4  = e & 31;
            cp16(&As[row * AST + q4 * 4], src + row * INP + q4 * 4);
        }
        CP_COMMIT();
    }

    int buf = 0;
    for (int tile = blockIdx.x; tile < NTILES; tile += NBLK) {
        const int nt = tile + NBLK;
        if (nt < NTILES) {
            // stage next tile into the other buffer (async, no regs)
            const float* src = inp + (size_t)nt * 128 * INP;
            float* dstb = As + (buf ^ 1) * AS_TILE;
            #pragma unroll
            for (int i = 0; i < 32; ++i) {
                int e = tid + i * 128;
                int row = e >> 5;
                int q4  = e & 31;
                cp16(&dstb[row * AST + q4 * 4], src + row * INP + q4 * 4);
            }
            CP_COMMIT();
            CP_WAIT1();   // current tile's group complete; next still in flight
        } else {
            CP_WAIT0();
        }
        __syncthreads();

        const float* Ab = As + buf * AS_TILE;

        unsigned long long acc[8][8];
        #pragma unroll
        for (int k = 0; k < 8; ++k)
            #pragma unroll
            for (int c = 0; c < 8; ++c) acc[k][c] = 0ull;

        #pragma unroll 4
        for (int q = 0; q < 32; ++q) {     // q = jp pair (k 4q..4q+3)
            ulonglong2 cw[8];
            #pragma unroll
            for (int c = 0; c < 8; ++c)
                cw[c] = Cq[q * 64 + c * 8 + ctx];
            ulonglong2 av[8];
            #pragma unroll
            for (int k = 0; k < 8; ++k)
                av[k] = *reinterpret_cast<const ulonglong2*>(
                    &Ab[(rt + 16 * k) * AST + 4 * q]);
            #pragma unroll
            for (int k = 0; k < 8; ++k)
                #pragma unroll
                for (int c = 0; c < 8; ++c) {
                    fma2(acc[k][c], av[k].x, cw[c].x);
                    fma2(acc[k][c], av[k].y, cw[c].y);
                }
        }

        #pragma unroll
        for (int k = 0; k < 8; ++k) {
            size_t row = (size_t)tile * 128 + rt + 16 * k;
            float4 o0, o1;
            o0.x = psum2(acc[k][0]); o0.y = psum2(acc[k][1]);
            o0.z = psum2(acc[k][2]); o0.w = psum2(acc[k][3]);
            o1.x = psum2(acc[k][4]); o1.y = psum2(acc[k][5]);
            o1.z = psum2(acc[k][6]); o1.w = psum2(acc[k][7]);
            float* dst = &g_drive[row * LAT + ctx * 8];
            reinterpret_cast<float4*>(dst)[0] = o0;
            reinterpret_cast<float4*>(dst)[1] = o1;
        }
        __syncthreads();   // all reads of Ab done before it is restaged
        buf ^= 1;
    }
}

// =====================================================================
// Kernel 2: scan (R11 verbatim — best known, 468.6 us). 128 x 512.
// =====================================================================
#define ZST 36
#define HST 18

__global__ void __launch_bounds__(512, 1)
recur_kernel(const float* __restrict__ Ag,   const float* __restrict__ W1g,
             const float* __restrict__ W2g,  const float* __restrict__ h1g,
             const float* __restrict__ h2g,  const float* __restrict__ Woutg,
             const float* __restrict__ boutg, float* __restrict__ outg) {
    __shared__ __align__(16) float zbuf[2][8 * ZST];
    __shared__ __align__(16) float hbuf[2][16 * HST];

    const int tid = threadIdx.x;
    const int gid = tid >> 8;
    const int c   = tid & 255;
    const int bat = blockIdx.x * 2 + gid;
    const int barid = 1 + gid;

    // phase1 mapping
    const int kc1 = c & 7;
    const int rg1 = c >> 3;
    const int b4a = (c >> 2) & 1;
    const int b2a = (c >> 1) & 1;
    const int hrow = 4 * rg1 + 2 * b4a + b2a;

    // phase2 mapping
    const int kc2 = c & 15;
    const int rg2 = c >> 4;
    const int b1b = c & 1;
    const int b2b = (c >> 1) & 1;
    const int lz  = 4 * rg2 + 2 * b1b + b2b;

    unsigned long long w2r[4][4];
    #pragma unroll
    for (int r = 0; r < 4; ++r)
        #pragma unroll
        for (int j = 0; j < 4; ++j)
            w2r[r][j] = *reinterpret_cast<const unsigned long long*>(
                &W2g[(4 * rg1 + r) * LAT + 8 * kc1 + 2 * j]);
    unsigned long long w1r[4][4];
    #pragma unroll
    for (int r = 0; r < 4; ++r)
        #pragma unroll
        for (int j = 0; j < 4; ++j)
            w1r[r][j] = *reinterpret_cast<const unsigned long long*>(
                &W1g[(4 * rg2 + r) * HID + 8 * kc2 + 2 * j]);

    const float h2c = h2g[hrow];
    const float Ac  = Ag[lz];
    const float h1c = h1g[lz];

    if ((c & 12) == 0) zbuf[gid][(lz >> 3) * ZST + (lz & 7)] = 0.0f;
    __syncthreads();

    const float* zptr = &zbuf[gid][kc1 * ZST];
    const unsigned long long* hptr =
        reinterpret_cast<const unsigned long long*>(&hbuf[gid][kc2 * HST]);

    float zprev = 0.0f;
    const size_t ubase = ((size_t)bat) * TT * LAT + lz;
    float u_cur = g_drive[ubase] + h1c;
    float u_nxt = g_drive[ubase + LAT] + h1c;

    const unsigned FULL = 0xffffffffu;

    for (int t = 0; t < TT; ++t) {
        const int tp = (t + 2 < TT) ? (t + 2) : (TT - 1);
        float u_fut = g_drive[ubase + (size_t)tp * LAT] + h1c;

        // ======== phase 1: hidden = relu(z @ W2^T + h2) ========
        {
            ulonglong2 za = *reinterpret_cast<const ulonglong2*>(zptr);
            ulonglong2 zb = *reinterpret_cast<const ulonglong2*>(zptr + 4);
            float p[4];
            #pragma unroll
            for (int r = 0; r < 4; ++r) {
                unsigned long long acc = 0ull;
                fma2(acc, za.x, w2r[r][0]);
                fma2(acc, za.y, w2r[r][1]);
                fma2(acc, zb.x, w2r[r][2]);
                fma2(acc, zb.y, w2r[r][3]);
                p[r] = psum2(acc);
            }
            float s0 = b4a ? p[0] : p[2];
            float r0 = __shfl_xor_sync(FULL, s0, 4);
            float s1 = b4a ? p[1] : p[3];
            float r1 = __shfl_xor_sync(FULL, s1, 4);
            float q0 = (b4a ? p[2] : p[0]) + r0;
            float q1 = (b4a ? p[3] : p[1]) + r1;
            float s2 = b2a ? q0 : q1;
            float r2 = __shfl_xor_sync(FULL, s2, 2);
            float s  = (b2a ? q1 : q0) + r2;
            s += __shfl_xor_sync(FULL, s, 1);
            float hval = fmaxf(s + h2c, 0.0f);
            if (!(c & 1))
                hbuf[gid][(hrow >> 3) * HST + (hrow & 7)] = hval;
        }
        gbar(barid);

        // ======== phase 2: z' = clip(z*A + hidden @ W1^T + (h1+u)) ========
        {
            unsigned long long h0 = hptr[0];
            unsigned long long h1v = hptr[1];
            unsigned long long h2v = hptr[2];
            unsigned long long h3v = hptr[3];
            float p[4];
            #pragma unroll
            for (int r = 0; r < 4; ++r) {
                unsigned long long acc = 0ull;
                fma2(acc, h0,  w1r[r][0]);
                fma2(acc, h1v, w1r[r][1]);
                fma2(acc, h2v, w1r[r][2]);
                fma2(acc, h3v, w1r[r][3]);
                p[r] = psum2(acc);
            }
            float s0 = b1b ? p[0] : p[2];
            float r0 = __shfl_xor_sync(FULL, s0, 1);
            float s1 = b1b ? p[1] : p[3];
            float r1 = __shfl_xor_sync(FULL, s1, 1);
            float q0 = (b1b ? p[2] : p[0]) + r0;
            float q1 = (b1b ? p[3] : p[1]) + r1;
            float s2 = b2b ? q0 : q1;
            float r2 = __shfl_xor_sync(FULL, s2, 2);
            float v  = (b2b ? q1 : q0) + r2;
            v += __shfl_xor_sync(FULL, v, 4);
            v += __shfl_xor_sync(FULL, v, 8);

            float zn = zprev * Ac + (v + u_cur);
            zn = fminf(5.0f, fmaxf(-5.0f, zn));
            zprev = zn;
            if ((c & 12) == 0)
                zbuf[gid][(lz >> 3) * ZST + (lz & 7)] = zn;
        }
        u_cur = u_nxt;
        u_nxt = u_fut;
        gbar(barid);
    }

    // ---- epilogue: out[bat][o] = zT . Wout[o] + bout[o]
    if (c < OUTD) {
        const int o = c;
        float acc = boutg[o];
        #pragma unroll
        for (int l = 0; l < LAT; ++l)
            acc += zbuf[gid][(l >> 3) * ZST + (l & 7)] * Woutg[o * LAT + l];
        outg[(size_t)bat * OUTD + o] = acc;
    }
}

// =====================================================================
extern "C" void kernel_launch(void* const* d_in, const int* in_sizes, int n_in,
                              void* d_out, int out_size) {
    (void)in_sizes; (void)n_in; (void)out_size;
    const float* inp   = (const float*)d_in[0];
    const float* Ag    = (const float*)d_in[1];
    const float* W1g   = (const float*)d_in[2];
    const float* W2g   = (const float*)d_in[3];
    const float* h1g   = (const float*)d_in[4];
    const float* h2g   = (const float*)d_in[5];
    const float* Cg    = (const float*)d_in[6];
    const float* Woutg = (const float*)d_in[7];
    const float* boutg = (const float*)d_in[8];
    float* outg = (float*)d_out;

    const int smem1 = 2 * AS_TILE * 4 + 32 * 64 * 16; // 135168 + 32768 = 167936
    cudaFuncSetAttribute(drive_kernel, cudaFuncAttributeMaxDynamicSharedMemorySize, smem1);

    drive_kernel<<<NBLK, 128, smem1>>>(inp, Cg);
    recur_kernel<<<BATCH / 2, 512>>>(Ag, W1g, W2g, h1g, h2g, Woutg, boutg, outg);
}

// round 14
// speedup vs baseline: 1.0828x; 1.0217x over previous
#include <cuda_runtime.h>
#include <cuda_bf16.h>

// Problem constants
#define BATCH 256
#define TT    1024
#define INP   128
#define LAT   64
#define HID   128
#define OUTD  32

// Scratch: drive[b][t][l] (fp32), 64 MB
__device__ float g_drive[(size_t)BATCH * TT * LAT];

// ---------- f32x2 helpers ----------
__device__ __forceinline__ void fma2(unsigned long long& acc,
                                     unsigned long long a,
                                     unsigned long long b) {
    asm("fma.rn.f32x2 %0, %1, %2, %0;" : "+l"(acc) : "l"(a), "l"(b));
}
__device__ __forceinline__ float psum2(unsigned long long v) {
    float lo, hi;
    asm("mov.b64 {%0,%1}, %2;" : "=f"(lo), "=f"(hi) : "l"(v));
    return lo + hi;
}
__device__ __forceinline__ unsigned long long pack2(float lo, float hi) {
    unsigned long long r;
    asm("mov.b64 %0, {%1,%2};" : "=l"(r) : "f"(lo), "f"(hi));
    return r;
}
__device__ __forceinline__ void gbar(int id) {
    asm volatile("bar.sync %0, 256;" :: "r"(id) : "memory");
}
// ---------- cp.async helpers ----------
__device__ __forceinline__ void cp16(void* smem_dst, const void* gsrc) {
    unsigned saddr = (unsigned)__cvta_generic_to_shared(smem_dst);
    asm volatile("cp.async.cg.shared.global [%0], [%1], 16;"
                 :: "r"(saddr), "l"(gsrc) : "memory");
}
#define CP_COMMIT() asm volatile("cp.async.commit_group;" ::: "memory")
#define CP_WAIT1()  asm volatile("cp.async.wait_group 1;" ::: "memory")
#define CP_WAIT0()  asm volatile("cp.async.wait_group 0;" ::: "memory")

// =====================================================================
// Kernel 1: PERSISTENT drive = input @ C^T  -> g_drive
// 148 blocks x 256 threads (2 warps/SMSP for latency cover).
// Double-buffered cp.async; 4x8 thread subtile over 128-row tiles.
// =====================================================================
#define AST 132
#define NTILES 2048
#define NBLK   148
#define AS_TILE (128 * AST)                 // floats per buffer

__global__ void __launch_bounds__(256, 1)
drive_kernel(const float* __restrict__ inp, const float* __restrict__ Cg) {
    extern __shared__ char dsm[];
    float*      As = reinterpret_cast<float*>(dsm);                      // [2][128*AST]
    ulonglong2* Cq = reinterpret_cast<ulonglong2*>(dsm + 2 * AS_TILE * 4);

    const int tid = threadIdx.x;

    // stage C once: Cq[q][(col&7)*8 + col>>3] = jp-pair of C[col][4q..4q+3]
    for (int idx = tid; idx < 2048; idx += 256) {
        int col = idx >> 5;
        int q4  = idx & 31;
        float4 v = reinterpret_cast<const float4*>(Cg)[idx];
        int csw = (col & 7) * 8 + (col >> 3);
        ulonglong2 p;
        p.x = pack2(v.x, v.y);
        p.y = pack2(v.z, v.w);
        Cq[q4 * 64 + csw] = p;
    }

    const int ctx = tid & 7;       // col group: cols ctx*8..+7
    const int rt  = tid >> 3;      // row base: rows rt + 32k, k=0..3

    // prologue: stage first tile into buf 0 (16 cp16 per thread)
    {
        const float* src = inp + (size_t)blockIdx.x * 128 * INP;
        #pragma unroll
        for (int i = 0; i < 16; ++i) {
            int e = tid + i * 256;
            int row = e >> 5;
            int q4  = e & 31;
            cp16(&As[row * AST + q4 * 4], src + row * INP + q4 * 4);
        }
        CP_COMMIT();
    }

    int buf = 0;
    for (int tile = blockIdx.x; tile < NTILES; tile += NBLK) {
        const int nt = tile + NBLK;
        if (nt < NTILES) {
            const float* src = inp + (size_t)nt * 128 * INP;
            float* dstb = As + (buf ^ 1) * AS_TILE;
            #pragma unroll
            for (int i = 0; i < 16; ++i) {
                int e = tid + i * 256;
                int row = e >> 5;
                int q4  = e & 31;
                cp16(&dstb[row * AST + q4 * 4], src + row * INP + q4 * 4);
            }
            CP_COMMIT();
            CP_WAIT1();   // current tile complete; next still in flight
        } else {
            CP_WAIT0();
        }
        __syncthreads();

        const float* Ab = As + buf * AS_TILE;

        unsigned long long acc[4][8];
        #pragma unroll
        for (int k = 0; k < 4; ++k)
            #pragma unroll
            for (int c = 0; c < 8; ++c) acc[k][c] = 0ull;

        #pragma unroll 4
        for (int q = 0; q < 32; ++q) {     // q = jp pair (k 4q..4q+3)
            ulonglong2 cw[8];
            #pragma unroll
            for (int c = 0; c < 8; ++c)
                cw[c] = Cq[q * 64 + c * 8 + ctx];
            ulonglong2 av[4];
            #pragma unroll
            for (int k = 0; k < 4; ++k)
                av[k] = *reinterpret_cast<const ulonglong2*>(
                    &Ab[(rt + 32 * k) * AST + 4 * q]);
            #pragma unroll
            for (int k = 0; k < 4; ++k)
                #pragma unroll
                for (int c = 0; c < 8; ++c) {
                    fma2(acc[k][c], av[k].x, cw[c].x);
                    fma2(acc[k][c], av[k].y, cw[c].y);
                }
        }

        #pragma unroll
        for (int k = 0; k < 4; ++k) {
            size_t row = (size_t)tile * 128 + rt + 32 * k;
            float4 o0, o1;
            o0.x = psum2(acc[k][0]); o0.y = psum2(acc[k][1]);
            o0.z = psum2(acc[k][2]); o0.w = psum2(acc[k][3]);
            o1.x = psum2(acc[k][4]); o1.y = psum2(acc[k][5]);
            o1.z = psum2(acc[k][6]); o1.w = psum2(acc[k][7]);
            float* dst = &g_drive[row * LAT + ctx * 8];
            reinterpret_cast<float4*>(dst)[0] = o0;
            reinterpret_cast<float4*>(dst)[1] = o1;
        }
        __syncthreads();   // all reads of Ab done before restage
        buf ^= 1;
    }
}

// =====================================================================
// Kernel 2: scan (R11 verbatim — best known, ~469 us). 128 x 512.
// =====================================================================
#define ZST 36
#define HST 18

__global__ void __launch_bounds__(512, 1)
recur_kernel(const float* __restrict__ Ag,   const float* __restrict__ W1g,
             const float* __restrict__ W2g,  const float* __restrict__ h1g,
             const float* __restrict__ h2g,  const float* __restrict__ Woutg,
             const float* __restrict__ boutg, float* __restrict__ outg) {
    __shared__ __align__(16) float zbuf[2][8 * ZST];
    __shared__ __align__(16) float hbuf[2][16 * HST];

    const int tid = threadIdx.x;
    const int gid = tid >> 8;
    const int c   = tid & 255;
    const int bat = blockIdx.x * 2 + gid;
    const int barid = 1 + gid;

    // phase1 mapping
    const int kc1 = c & 7;
    const int rg1 = c >> 3;
    const int b4a = (c >> 2) & 1;
    const int b2a = (c >> 1) & 1;
    const int hrow = 4 * rg1 + 2 * b4a + b2a;

    // phase2 mapping
    const int kc2 = c & 15;
    const int rg2 = c >> 4;
    const int b1b = c & 1;
    const int b2b = (c >> 1) & 1;
    const int lz  = 4 * rg2 + 2 * b1b + b2b;

    unsigned long long w2r[4][4];
    #pragma unroll
    for (int r = 0; r < 4; ++r)
        #pragma unroll
        for (int j = 0; j < 4; ++j)
            w2r[r][j] = *reinterpret_cast<const unsigned long long*>(
                &W2g[(4 * rg1 + r) * LAT + 8 * kc1 + 2 * j]);
    unsigned long long w1r[4][4];
    #pragma unroll
    for (int r = 0; r < 4; ++r)
        #pragma unroll
        for (int j = 0; j < 4; ++j)
            w1r[r][j] = *reinterpret_cast<const unsigned long long*>(
                &W1g[(4 * rg2 + r) * HID + 8 * kc2 + 2 * j]);

    const float h2c = h2g[hrow];
    const float Ac  = Ag[lz];
    const float h1c = h1g[lz];

    if ((c & 12) == 0) zbuf[gid][(lz >> 3) * ZST + (lz & 7)] = 0.0f;
    __syncthreads();

    const float* zptr = &zbuf[gid][kc1 * ZST];
    const unsigned long long* hptr =
        reinterpret_cast<const unsigned long long*>(&hbuf[gid][kc2 * HST]);

    float zprev = 0.0f;
    const size_t ubase = ((size_t)bat) * TT * LAT + lz;
    float u_cur = g_drive[ubase] + h1c;
    float u_nxt = g_drive[ubase + LAT] + h1c;

    const unsigned FULL = 0xffffffffu;

    for (int t = 0; t < TT; ++t) {
        const int tp = (t + 2 < TT) ? (t + 2) : (TT - 1);
        float u_fut = g_drive[ubase + (size_t)tp * LAT] + h1c;

        // ======== phase 1: hidden = relu(z @ W2^T + h2) ========
        {
            ulonglong2 za = *reinterpret_cast<const ulonglong2*>(zptr);
            ulonglong2 zb = *reinterpret_cast<const ulonglong2*>(zptr + 4);
            float p[4];
            #pragma unroll
            for (int r = 0; r < 4; ++r) {
                unsigned long long acc = 0ull;
                fma2(acc, za.x, w2r[r][0]);
                fma2(acc, za.y, w2r[r][1]);
                fma2(acc, zb.x, w2r[r][2]);
                fma2(acc, zb.y, w2r[r][3]);
                p[r] = psum2(acc);
            }
            float s0 = b4a ? p[0] : p[2];
            float r0 = __shfl_xor_sync(FULL, s0, 4);
            float s1 = b4a ? p[1] : p[3];
            float r1 = __shfl_xor_sync(FULL, s1, 4);
            float q0 = (b4a ? p[2] : p[0]) + r0;
            float q1 = (b4a ? p[3] : p[1]) + r1;
            float s2 = b2a ? q0 : q1;
            float r2 = __shfl_xor_sync(FULL, s2, 2);
            float s  = (b2a ? q1 : q0) + r2;
            s += __shfl_xor_sync(FULL, s, 1);
            float hval = fmaxf(s + h2c, 0.0f);
            if (!(c & 1))
                hbuf[gid][(hrow >> 3) * HST + (hrow & 7)] = hval;
        }
        gbar(barid);

        // ======== phase 2: z' = clip(z*A + hidden @ W1^T + (h1+u)) ========
        {
            unsigned long long h0 = hptr[0];
            unsigned long long h1v = hptr[1];
            unsigned long long h2v = hptr[2];
            unsigned long long h3v = hptr[3];
            float p[4];
            #pragma unroll
            for (int r = 0; r < 4; ++r) {
                unsigned long long acc = 0ull;
                fma2(acc, h0,  w1r[r][0]);
                fma2(acc, h1v, w1r[r][1]);
                fma2(acc, h2v, w1r[r][2]);
                fma2(acc, h3v, w1r[r][3]);
                p[r] = psum2(acc);
            }
            float s0 = b1b ? p[0] : p[2];
            float r0 = __shfl_xor_sync(FULL, s0, 1);
            float s1 = b1b ? p[1] : p[3];
            float r1 = __shfl_xor_sync(FULL, s1, 1);
            float q0 = (b1b ? p[2] : p[0]) + r0;
            float q1 = (b1b ? p[3] : p[1]) + r1;
            float s2 = b2b ? q0 : q1;
            float r2 = __shfl_xor_sync(FULL, s2, 2);
            float v  = (b2b ? q1 : q0) + r2;
            v += __shfl_xor_sync(FULL, v, 4);
            v += __shfl_xor_sync(FULL, v, 8);

            float zn = zprev * Ac + (v + u_cur);
            zn = fminf(5.0f, fmaxf(-5.0f, zn));
            zprev = zn;
            if ((c & 12) == 0)
                zbuf[gid][(lz >> 3) * ZST + (lz & 7)] = zn;
        }
        u_cur = u_nxt;
        u_nxt = u_fut;
        gbar(barid);
    }

    // ---- epilogue: out[bat][o] = zT . Wout[o] + bout[o]
    if (c < OUTD) {
        const int o = c;
        float acc = boutg[o];
        #pragma unroll
        for (int l = 0; l < LAT; ++l)
            acc += zbuf[gid][(l >> 3) * ZST + (l & 7)] * Woutg[o * LAT + l];
        outg[(size_t)bat * OUTD + o] = acc;
    }
}

// =====================================================================
extern "C" void kernel_launch(void* const* d_in, const int* in_sizes, int n_in,
                              void* d_out, int out_size) {
    (void)in_sizes; (void)n_in; (void)out_size;
    const float* inp   = (const float*)d_in[0];
    const float* Ag    = (const float*)d_in[1];
    const float* W1g   = (const float*)d_in[2];
    const float* W2g   = (const float*)d_in[3];
    const float* h1g   = (const float*)d_in[4];
    const float* h2g   = (const float*)d_in[5];
    const float* Cg    = (const float*)d_in[6];
    const float* Woutg = (const float*)d_in[7];
    const float* boutg = (const float*)d_in[8];
    float* outg = (float*)d_out;

    const int smem1 = 2 * AS_TILE * 4 + 32 * 64 * 16; // 135168 + 32768 = 167936
    cudaFuncSetAttribute(drive_kernel, cudaFuncAttributeMaxDynamicSharedMemorySize, smem1);

    drive_kernel<<<NBLK, 256, smem1>>>(inp, Cg);
    recur_kernel<<<BATCH / 2, 512>>>(Ag, W1g, W2g, h1g, h2g, Woutg, boutg, outg);
}

// round 15
// speedup vs baseline: 1.3104x; 1.2102x over previous
#include <cuda_runtime.h>
#include <cuda_bf16.h>

// Problem constants
#define BATCH 256
#define TT    1024
#define INP   128
#define LAT   64
#define HID   128
#define OUTD  32

// Scratch: drive[b][t][l] (fp32), 64 MB
__device__ float g_drive[(size_t)BATCH * TT * LAT];

// ---------- f32x2 helpers ----------
__device__ __forceinline__ void fma2(unsigned long long& acc,
                                     unsigned long long a,
                                     unsigned long long b) {
    asm("fma.rn.f32x2 %0, %1, %2, %0;" : "+l"(acc) : "l"(a), "l"(b));
}
__device__ __forceinline__ float psum2(unsigned long long v) {
    float lo, hi;
    asm("mov.b64 {%0,%1}, %2;" : "=f"(lo), "=f"(hi) : "l"(v));
    return lo + hi;
}
__device__ __forceinline__ unsigned long long pack2(float lo, float hi) {
    unsigned long long r;
    asm("mov.b64 %0, {%1,%2};" : "=l"(r) : "f"(lo), "f"(hi));
    return r;
}
__device__ __forceinline__ void bsync(int id) {
    asm volatile("bar.sync %0, 256;" :: "r"(id) : "memory");
}
__device__ __forceinline__ void barrive(int id) {
    asm volatile("bar.arrive %0, 256;" :: "r"(id) : "memory");
}
// ---------- cp.async helpers ----------
__device__ __forceinline__ void cp16(void* smem_dst, const void* gsrc) {
    unsigned saddr = (unsigned)__cvta_generic_to_shared(smem_dst);
    asm volatile("cp.async.cg.shared.global [%0], [%1], 16;"
                 :: "r"(saddr), "l"(gsrc) : "memory");
}
#define CP_COMMIT() asm volatile("cp.async.commit_group;" ::: "memory")
#define CP_WAIT1()  asm volatile("cp.async.wait_group 1;" ::: "memory")
#define CP_WAIT0()  asm volatile("cp.async.wait_group 0;" ::: "memory")

// =====================================================================
// Kernel 1: PERSISTENT drive = input @ C^T  (R14 verbatim)
// 148 blocks x 256 threads; double-buffered cp.async; 4x8 subtile.
// =====================================================================
#define AST 132
#define NTILES 2048
#define NBLK   148
#define AS_TILE (128 * AST)

__global__ void __launch_bounds__(256, 1)
drive_kernel(const float* __restrict__ inp, const float* __restrict__ Cg) {
    extern __shared__ char dsm[];
    float*      As = reinterpret_cast<float*>(dsm);
    ulonglong2* Cq = reinterpret_cast<ulonglong2*>(dsm + 2 * AS_TILE * 4);

    const int tid = threadIdx.x;

    for (int idx = tid; idx < 2048; idx += 256) {
        int col = idx >> 5;
        int q4  = idx & 31;
        float4 v = reinterpret_cast<const float4*>(Cg)[idx];
        int csw = (col & 7) * 8 + (col >> 3);
        ulonglong2 p;
        p.x = pack2(v.x, v.y);
        p.y = pack2(v.z, v.w);
        Cq[q4 * 64 + csw] = p;
    }

    const int ctx = tid & 7;
    const int rt  = tid >> 3;

    {
        const float* src = inp + (size_t)blockIdx.x * 128 * INP;
        #pragma unroll
        for (int i = 0; i < 16; ++i) {
            int e = tid + i * 256;
            int row = e >> 5;
            int q4  = e & 31;
            cp16(&As[row * AST + q4 * 4], src + row * INP + q4 * 4);
        }
        CP_COMMIT();
    }

    int buf = 0;
    for (int tile = blockIdx.x; tile < NTILES; tile += NBLK) {
        const int nt = tile + NBLK;
        if (nt < NTILES) {
            const float* src = inp + (size_t)nt * 128 * INP;
            float* dstb = As + (buf ^ 1) * AS_TILE;
            #pragma unroll
            for (int i = 0; i < 16; ++i) {
                int e = tid + i * 256;
                int row = e >> 5;
                int q4  = e & 31;
                cp16(&dstb[row * AST + q4 * 4], src + row * INP + q4 * 4);
            }
            CP_COMMIT();
            CP_WAIT1();
        } else {
            CP_WAIT0();
        }
        __syncthreads();

        const float* Ab = As + buf * AS_TILE;

        unsigned long long acc[4][8];
        #pragma unroll
        for (int k = 0; k < 4; ++k)
            #pragma unroll
            for (int c = 0; c < 8; ++c) acc[k][c] = 0ull;

        #pragma unroll 4
        for (int q = 0; q < 32; ++q) {
            ulonglong2 cw[8];
            #pragma unroll
            for (int c = 0; c < 8; ++c)
                cw[c] = Cq[q * 64 + c * 8 + ctx];
            ulonglong2 av[4];
            #pragma unroll
            for (int k = 0; k < 4; ++k)
                av[k] = *reinterpret_cast<const ulonglong2*>(
                    &Ab[(rt + 32 * k) * AST + 4 * q]);
            #pragma unroll
            for (int k = 0; k < 4; ++k)
                #pragma unroll
                for (int c = 0; c < 8; ++c) {
                    fma2(acc[k][c], av[k].x, cw[c].x);
                    fma2(acc[k][c], av[k].y, cw[c].y);
                }
        }

        #pragma unroll
        for (int k = 0; k < 4; ++k) {
            size_t row = (size_t)tile * 128 + rt + 32 * k;
            float4 o0, o1;
            o0.x = psum2(acc[k][0]); o0.y = psum2(acc[k][1]);
            o0.z = psum2(acc[k][2]); o0.w = psum2(acc[k][3]);
            o1.x = psum2(acc[k][4]); o1.y = psum2(acc[k][5]);
            o1.z = psum2(acc[k][6]); o1.w = psum2(acc[k][7]);
            float* dst = &g_drive[row * LAT + ctx * 8];
            reinterpret_cast<float4*>(dst)[0] = o0;
            reinterpret_cast<float4*>(dst)[1] = o1;
        }
        __syncthreads();
        buf ^= 1;
    }
}

// =====================================================================
// Kernel 2: WARP-SPECIALIZED scan. 128 blocks x 512 threads = 2 chains.
// Each chain: warps 0-3 = phase1 (h = relu(z W2^T + h2)),
//             warps 4-7 = phase2 (z' = clip(zA + h W1^T + h1 + u)).
// Producer/consumer via bar.arrive / bar.sync ping-pong (2 bars/chain).
// z & h double-buffered by step parity; 16-float chunks at stride 36
// (LDS.128 quad-conflict-free). Weights fully register-resident.
// =====================================================================
#define CST 36   // chunk stride (floats): quads 9k mod 8 distinct

__global__ void __launch_bounds__(512, 1)
recur_kernel(const float* __restrict__ Ag,   const float* __restrict__ W1g,
             const float* __restrict__ W2g,  const float* __restrict__ h1g,
             const float* __restrict__ h2g,  const float* __restrict__ Woutg,
             const float* __restrict__ boutg, float* __restrict__ outg) {
    __shared__ __align__(16) float zbuf[2][2][4 * CST];   // [chain][parity]
    __shared__ __align__(16) float hbuf[2][2][8 * CST];

    const int tid = threadIdx.x;
    const int gid = tid >> 8;          // chain
    const int c   = tid & 255;
    const int bat = blockIdx.x * 2 + gid;
    const int barA = 1 + 2 * gid;      // h-ready
    const int barB = 2 + 2 * gid;      // z-ready
    const int role = c >> 7;           // 0 = phase1 warps, 1 = phase2 warps
    const int cl   = c & 127;

    const unsigned FULL = 0xffffffffu;

    // zero z buffers (both parities; only parity 0 strictly needed)
    for (int i = tid; i < 2 * 2 * 4 * CST; i += 512)
        reinterpret_cast<float*>(zbuf)[i] = 0.0f;
    __syncthreads();

    if (role == 0) {
        // ---------------- phase1 warps ----------------
        const int kc1 = cl & 3;            // z chunk (16 floats)
        const int rg1 = cl >> 2;           // row group (4 rows)
        const int b2  = (cl >> 1) & 1;
        const int b1  = cl & 1;
        const int hrow = cl;               // = 4*rg1 + 2*b2 + b1

        unsigned long long w2r[4][8];
        #pragma unroll
        for (int r = 0; r < 4; ++r)
            #pragma unroll
            for (int j = 0; j < 8; ++j)
                w2r[r][j] = *reinterpret_cast<const unsigned long long*>(
                    &W2g[(4 * rg1 + r) * LAT + 16 * kc1 + 2 * j]);
        const float h2c = h2g[hrow];
        const int hsl = (hrow >> 4) * CST + (hrow & 15);

        for (int t = 0; t < TT; ++t) {
            if (t) bsync(barB);            // wait z(t)
            const ulonglong2* zq = reinterpret_cast<const ulonglong2*>(
                &zbuf[gid][t & 1][kc1 * CST]);
            ulonglong2 z0 = zq[0], z1 = zq[1], z2 = zq[2], z3 = zq[3];
            float p[4];
            #pragma unroll
            for (int r = 0; r < 4; ++r) {
                unsigned long long a = 0, b = 0;
                fma2(a, z0.x, w2r[r][0]); fma2(b, z0.y, w2r[r][1]);
                fma2(a, z1.x, w2r[r][2]); fma2(b, z1.y, w2r[r][3]);
                fma2(a, z2.x, w2r[r][4]); fma2(b, z2.y, w2r[r][5]);
                fma2(a, z3.x, w2r[r][6]); fma2(b, z3.y, w2r[r][7]);
                p[r] = psum2(a) + psum2(b);
            }
            // reduce-scatter over 4 kc1 lanes (xor2 then xor1)
            float s0 = b2 ? p[0] : p[2];
            float r0 = __shfl_xor_sync(FULL, s0, 2);
            float s1 = b2 ? p[1] : p[3];
            float r1 = __shfl_xor_sync(FULL, s1, 2);
            float q0 = (b2 ? p[2] : p[0]) + r0;
            float q1 = (b2 ? p[3] : p[1]) + r1;
            float s2 = b1 ? q0 : q1;
            float r2 = __shfl_xor_sync(FULL, s2, 1);
            float s  = (b1 ? q1 : q0) + r2;
            hbuf[gid][t & 1][hsl] = fmaxf(s + h2c, 0.0f);
            barrive(barA);                 // h(t) ready
        }
    } else {
        // ---------------- phase2 warps ----------------
        const int kc2 = cl & 7;            // h chunk (16 floats)
        const int rg2 = cl >> 3;           // row group (4 rows)
        const int b4  = (cl >> 2) & 1;
        const int b2r = (cl >> 1) & 1;
        const int lz  = 4 * rg2 + 2 * b4 + b2r;

        unsigned long long w1r[4][8];
        #pragma unroll
        for (int r = 0; r < 4; ++r)
            #pragma unroll
            for (int j = 0; j < 8; ++j)
                w1r[r][j] = *reinterpret_cast<const unsigned long long*>(
                    &W1g[(4 * rg2 + r) * HID + 16 * kc2 + 2 * j]);
        const float Ac  = Ag[lz];
        const float h1c = h1g[lz];
        const int zsl = (lz >> 4) * CST + (lz & 15);

        float zprev = 0.0f;
        const size_t ubase = ((size_t)bat) * TT * LAT + lz;
        float u_cur = g_drive[ubase] + h1c;
        float u_nxt = g_drive[ubase + LAT] + h1c;

        for (int t = 0; t < TT; ++t) {
            const int tp = (t + 2 < TT) ? (t + 2) : (TT - 1);
            float u_fut = g_drive[ubase + (size_t)tp * LAT] + h1c;

            bsync(barA);                   // wait h(t)
            const ulonglong2* hq = reinterpret_cast<const ulonglong2*>(
                &hbuf[gid][t & 1][kc2 * CST]);
            ulonglong2 h0 = hq[0], h1v = hq[1], h2v = hq[2], h3v = hq[3];
            float p[4];
            #pragma unroll
            for (int r = 0; r < 4; ++r) {
                unsigned long long a = 0, b = 0;
                fma2(a, h0.x,  w1r[r][0]); fma2(b, h0.y,  w1r[r][1]);
                fma2(a, h1v.x, w1r[r][2]); fma2(b, h1v.y, w1r[r][3]);
                fma2(a, h2v.x, w1r[r][4]); fma2(b, h2v.y, w1r[r][5]);
                fma2(a, h3v.x, w1r[r][6]); fma2(b, h3v.y, w1r[r][7]);
                p[r] = psum2(a) + psum2(b);
            }
            // reduce-scatter over 8 kc2 lanes (xor4, xor2, xor1-broadcast)
            float s0 = b4 ? p[0] : p[2];
            float r0 = __shfl_xor_sync(FULL, s0, 4);
            float s1 = b4 ? p[1] : p[3];
            float r1 = __shfl_xor_sync(FULL, s1, 4);
            float q0 = (b4 ? p[2] : p[0]) + r0;
            float q1 = (b4 ? p[3] : p[1]) + r1;
            float s2 = b2r ? q0 : q1;
            float r2 = __shfl_xor_sync(FULL, s2, 2);
            float v  = (b2r ? q1 : q0) + r2;
            v += __shfl_xor_sync(FULL, v, 1);

            float zn = zprev * Ac + (v + u_cur);
            zn = fminf(5.0f, fmaxf(-5.0f, zn));
            zprev = zn;
            if (!(cl & 1))
                zbuf[gid][(t + 1) & 1][zsl] = zn;
            barrive(barB);                 // z(t+1) ready

            u_cur = u_nxt;
            u_nxt = u_fut;
        }
    }

    __syncthreads();   // final z (parity 0) visible to all

    // ---- epilogue: out[bat][o] = zT . Wout[o] + bout[o]
    if (c < OUTD) {
        const int o = c;
        float acc = boutg[o];
        #pragma unroll
        for (int l = 0; l < LAT; ++l)
            acc += zbuf[gid][0][(l >> 4) * CST + (l & 15)] * Woutg[o * LAT + l];
        outg[(size_t)bat * OUTD + o] = acc;
    }
}

// =====================================================================
extern "C" void kernel_launch(void* const* d_in, const int* in_sizes, int n_in,
                              void* d_out, int out_size) {
    (void)in_sizes; (void)n_in; (void)out_size;
    const float* inp   = (const float*)d_in[0];
    const float* Ag    = (const float*)d_in[1];
    const float* W1g   = (const float*)d_in[2];
    const float* W2g   = (const float*)d_in[3];
    const float* h1g   = (const float*)d_in[4];
    const float* h2g   = (const float*)d_in[5];
    const float* Cg    = (const float*)d_in[6];
    const float* Woutg = (const float*)d_in[7];
    const float* boutg = (const float*)d_in[8];
    float* outg = (float*)d_out;

    const int smem1 = 2 * AS_TILE * 4 + 32 * 64 * 16; // 167936 B
    cudaFuncSetAttribute(drive_kernel, cudaFuncAttributeMaxDynamicSharedMemorySize, smem1);

    drive_kernel<<<NBLK, 256, smem1>>>(inp, Cg);
    recur_kernel<<<BATCH / 2, 512>>>(Ag, W1g, W2g, h1g, h2g, Woutg, boutg, outg);
}